// round 1
// baseline (speedup 1.0000x reference)
#include <cuda_runtime.h>
#include <math.h>

// Problem constants (fixed by the reference dataset)
#define T_   6400
#define Dm   512
#define Nn   2048
#define Hh   4
#define NBUCK 128

// offsets = [0, 2048, 3584, 4608, 6400]; lengths all multiples of 64.
__constant__ int c_off[5] = {0, 2048, 3584, 4608, 6400};

// Scratch (static device globals — no allocation allowed)
__device__ float g_xn[(size_t)T_ * Dm];       // ln(x)
__device__ float g_h[(size_t)T_ * 1024];      // silu(ln(x) @ uvqk): [u|v|q|k]
__device__ float g_attn[(size_t)T_ * 256];    // attention output (jagged)
__device__ float g_oin[(size_t)T_ * 256];     // u * ln(attn)

// ---------------------------------------------------------------------------
// LayerNorm over D=512 (no affine, biased var)
// ---------------------------------------------------------------------------
__global__ __launch_bounds__(256) void ln_x_kernel(const float* __restrict__ x,
                                                   float* __restrict__ xn) {
    int t = blockIdx.x, tid = threadIdx.x;
    const float* row = x + (size_t)t * Dm;
    float v0 = row[tid], v1 = row[tid + 256];
    float s = v0 + v1, q = v0 * v0 + v1 * v1;
#pragma unroll
    for (int o = 16; o > 0; o >>= 1) {
        s += __shfl_down_sync(0xffffffffu, s, o);
        q += __shfl_down_sync(0xffffffffu, q, o);
    }
    __shared__ float rs[8], rq[8], mv[2];
    if ((tid & 31) == 0) { rs[tid >> 5] = s; rq[tid >> 5] = q; }
    __syncthreads();
    if (tid == 0) {
        float S = 0.f, Q = 0.f;
#pragma unroll
        for (int i = 0; i < 8; i++) { S += rs[i]; Q += rq[i]; }
        float m = S * (1.f / Dm);
        mv[0] = m;
        mv[1] = rsqrtf(Q * (1.f / Dm) - m * m + 1e-6f);
    }
    __syncthreads();
    float m = mv[0], r = mv[1];
    float* o = xn + (size_t)t * Dm;
    o[tid] = (v0 - m) * r;
    o[tid + 256] = (v1 - m) * r;
}

// ---------------------------------------------------------------------------
// h = silu(xn @ uvqk)   A:[6400,512] B:[512,1024] -> C:[6400,1024]
// 64x64 tiles, 16 k-step, 256 threads, 4x4 micro-tile
// ---------------------------------------------------------------------------
__global__ __launch_bounds__(256) void gemm_silu_kernel(const float* __restrict__ A,
                                                        const float* __restrict__ Bm,
                                                        float* __restrict__ C) {
    __shared__ float sA[16][65];  // sA[k][row]
    __shared__ float sB[16][65];  // sB[k][col]
    int bm = blockIdx.y * 64, bn = blockIdx.x * 64;
    int tid = threadIdx.x, tx = tid & 15, ty = tid >> 4;
    float acc[4][4] = {};
    for (int k0 = 0; k0 < Dm; k0 += 16) {
        for (int i = tid; i < 1024; i += 256) {
            int r = i >> 4, kk = i & 15;
            sA[kk][r] = A[(size_t)(bm + r) * Dm + k0 + kk];
        }
        for (int i = tid; i < 1024; i += 256) {
            int kk = i >> 6, c = i & 63;
            sB[kk][c] = Bm[(size_t)(k0 + kk) * 1024 + bn + c];
        }
        __syncthreads();
#pragma unroll
        for (int kk = 0; kk < 16; kk++) {
            float a[4], b[4];
#pragma unroll
            for (int i = 0; i < 4; i++) a[i] = sA[kk][ty * 4 + i];
#pragma unroll
            for (int j = 0; j < 4; j++) b[j] = sB[kk][tx * 4 + j];
#pragma unroll
            for (int i = 0; i < 4; i++)
#pragma unroll
                for (int j = 0; j < 4; j++) acc[i][j] = fmaf(a[i], b[j], acc[i][j]);
        }
        __syncthreads();
    }
#pragma unroll
    for (int i = 0; i < 4; i++) {
        int r = bm + ty * 4 + i;
#pragma unroll
        for (int j = 0; j < 4; j++) {
            float s = acc[i][j];
            s = s / (1.f + expf(-s));  // silu
            C[(size_t)r * 1024 + bn + tx * 4 + j] = s;
        }
    }
}

// ---------------------------------------------------------------------------
// Jagged causal attention, silu scoring + bucketed time-delta bias.
// Grid: (qtile<=32, batch=4, head=4). 64x64 tiles. Q/K/V read directly from
// the jagged h buffer (no padding needed: causal keys are always valid).
// ---------------------------------------------------------------------------
#define SQ_OFF 0
#define SK_OFF (64 * 65)
#define SV_OFF (2 * 64 * 65)
#define SS_OFF (3 * 64 * 65)
#define SW_OFF (4 * 64 * 65)
#define STQ_OFF (SW_OFF + 132)          // float index where int area starts
#define ATTN_SMEM ((4 * 64 * 65 + 132) * 4 + 128 * 4)

__global__ __launch_bounds__(256) void attn_kernel(const float* __restrict__ h,
                                                   const int* __restrict__ ts,
                                                   const float* __restrict__ ts_w,
                                                   float* __restrict__ attn) {
    int tile = blockIdx.x, b = blockIdx.y, head = blockIdx.z;
    int base = c_off[b];
    int len = c_off[b + 1] - base;
    int q0 = tile * 64;
    if (q0 >= len) return;

    extern __shared__ float sm[];
    float* sQ = sm + SQ_OFF;
    float* sK = sm + SK_OFF;
    float* sV = sm + SV_OFF;
    float* sS = sm + SS_OFF;
    float* sW = sm + SW_OFF;
    int* sTq = (int*)(sm + STQ_OFF);
    int* sTk = sTq + 64;

    int tid = threadIdx.x;
    for (int i = tid; i < NBUCK + 1; i += 256) sW[i] = ts_w[i];
    if (tid < 64) sTq[tid] = ts[b * Nn + q0 + tid];

    // Load Q tile (64 rows x 64 dims) via float4
    {
        int hofQ = 512 + head * 64;
        for (int i = tid; i < 64 * 16; i += 256) {
            int r = i >> 4, d4 = (i & 15) * 4;
            float4 v = *reinterpret_cast<const float4*>(
                &h[(size_t)(base + q0 + r) * 1024 + hofQ + d4]);
            float* dst = &sQ[r * 65 + d4];
            dst[0] = v.x; dst[1] = v.y; dst[2] = v.z; dst[3] = v.w;
        }
    }

    int tx = tid & 15, ty = tid >> 4;
    int r0 = ty * 4, c0 = tx * 4;
    float o[4][4] = {};

    int hofK = 768 + head * 64, hofV = 256 + head * 64;
    for (int kt = 0; kt <= tile; ++kt) {
        __syncthreads();  // protects sK/sV/sS reuse (and initial Q/sTq load)
        int k0 = kt * 64;
        if (tid < 64) sTk[tid] = ts[b * Nn + k0 + tid];
        for (int i = tid; i < 64 * 16; i += 256) {
            int r = i >> 4, d4 = (i & 15) * 4;
            size_t rowb = (size_t)(base + k0 + r) * 1024;
            float4 kv = *reinterpret_cast<const float4*>(&h[rowb + hofK + d4]);
            float4 vv = *reinterpret_cast<const float4*>(&h[rowb + hofV + d4]);
            float* dk = &sK[r * 65 + d4];
            dk[0] = kv.x; dk[1] = kv.y; dk[2] = kv.z; dk[3] = kv.w;
            float* dv = &sV[r * 65 + d4];
            dv[0] = vv.x; dv[1] = vv.y; dv[2] = vv.z; dv[3] = vv.w;
        }
        __syncthreads();

        // S = Q K^T (4x4 micro)
        float acc[4][4] = {};
#pragma unroll 8
        for (int kk = 0; kk < 64; kk++) {
            float qv[4], kv[4];
#pragma unroll
            for (int i = 0; i < 4; i++) qv[i] = sQ[(r0 + i) * 65 + kk];
#pragma unroll
            for (int j = 0; j < 4; j++) kv[j] = sK[(c0 + j) * 65 + kk];
#pragma unroll
            for (int i = 0; i < 4; i++)
#pragma unroll
                for (int j = 0; j < 4; j++) acc[i][j] = fmaf(qv[i], kv[j], acc[i][j]);
        }
        // bias + silu + /N + causal mask -> sS
#pragma unroll
        for (int i = 0; i < 4; i++) {
            int qn = q0 + r0 + i;
            int tq = sTq[r0 + i];
#pragma unroll
            for (int j = 0; j < 4; j++) {
                int kn = k0 + c0 + j;
                float s = 0.f;
                if (kn <= qn) {
                    float ad = fabsf((float)(tq - sTk[c0 + j]));
                    int bucket = (int)floorf(log1pf(ad));
                    bucket = min(max(bucket, 0), NBUCK);
                    s = acc[i][j] + sW[bucket];
                    s = s / (1.f + expf(-s));
                    s *= (1.0f / (float)Nn);
                }
                sS[(r0 + i) * 65 + c0 + j] = s;
            }
        }
        __syncthreads();

        // O += S V
#pragma unroll 8
        for (int kk = 0; kk < 64; kk++) {
            float sv[4], vv[4];
#pragma unroll
            for (int i = 0; i < 4; i++) sv[i] = sS[(r0 + i) * 65 + kk];
#pragma unroll
            for (int j = 0; j < 4; j++) vv[j] = sV[kk * 65 + c0 + j];
#pragma unroll
            for (int i = 0; i < 4; i++)
#pragma unroll
                for (int j = 0; j < 4; j++) o[i][j] = fmaf(sv[i], vv[j], o[i][j]);
        }
    }

    // write jagged attn output [t, head*64 + c]
#pragma unroll
    for (int i = 0; i < 4; i++) {
        int qn = q0 + r0 + i;
        if (qn < len) {
            float* dst = &attn[(size_t)(base + qn) * 256 + head * 64 + c0];
#pragma unroll
            for (int j = 0; j < 4; j++) dst[j] = o[i][j];
        }
    }
}

// ---------------------------------------------------------------------------
// o_in = u * ln(attn)   (rows of 256; u = h[:, 0:256])
// ---------------------------------------------------------------------------
__global__ __launch_bounds__(256) void ln_u_kernel(const float* __restrict__ attn,
                                                   const float* __restrict__ h,
                                                   float* __restrict__ oin) {
    int t = blockIdx.x, tid = threadIdx.x;
    float v = attn[(size_t)t * 256 + tid];
    float s = v, q = v * v;
#pragma unroll
    for (int o = 16; o > 0; o >>= 1) {
        s += __shfl_down_sync(0xffffffffu, s, o);
        q += __shfl_down_sync(0xffffffffu, q, o);
    }
    __shared__ float rs[8], rq[8], mv[2];
    if ((tid & 31) == 0) { rs[tid >> 5] = s; rq[tid >> 5] = q; }
    __syncthreads();
    if (tid == 0) {
        float S = 0.f, Q = 0.f;
#pragma unroll
        for (int i = 0; i < 8; i++) { S += rs[i]; Q += rq[i]; }
        float m = S * (1.f / 256.f);
        mv[0] = m;
        mv[1] = rsqrtf(Q * (1.f / 256.f) - m * m + 1e-6f);
    }
    __syncthreads();
    float ln = (v - mv[0]) * mv[1];
    oin[(size_t)t * 256 + tid] = h[(size_t)t * 1024 + tid] * ln;
}

// ---------------------------------------------------------------------------
// out = o_in @ o_w^T + o_b + x    A:[6400,256]  W:[512,256] (row = out-dim)
// ---------------------------------------------------------------------------
__global__ __launch_bounds__(256) void gemm_out_kernel(const float* __restrict__ A,
                                                       const float* __restrict__ W,
                                                       const float* __restrict__ bias,
                                                       const float* __restrict__ x,
                                                       float* __restrict__ out) {
    __shared__ float sA[16][65];
    __shared__ float sB[16][65];
    int bm = blockIdx.y * 64, bn = blockIdx.x * 64;
    int tid = threadIdx.x, tx = tid & 15, ty = tid >> 4;
    float acc[4][4] = {};
    for (int k0 = 0; k0 < 256; k0 += 16) {
        for (int i = tid; i < 1024; i += 256) {
            int r = i >> 4, kk = i & 15;
            sA[kk][r] = A[(size_t)(bm + r) * 256 + k0 + kk];
        }
        for (int i = tid; i < 1024; i += 256) {
            int c = i >> 4, kk = i & 15;
            sB[kk][c] = W[(size_t)(bn + c) * 256 + k0 + kk];
        }
        __syncthreads();
#pragma unroll
        for (int kk = 0; kk < 16; kk++) {
            float a[4], b[4];
#pragma unroll
            for (int i = 0; i < 4; i++) a[i] = sA[kk][ty * 4 + i];
#pragma unroll
            for (int j = 0; j < 4; j++) b[j] = sB[kk][tx * 4 + j];
#pragma unroll
            for (int i = 0; i < 4; i++)
#pragma unroll
                for (int j = 0; j < 4; j++) acc[i][j] = fmaf(a[i], b[j], acc[i][j]);
        }
        __syncthreads();
    }
#pragma unroll
    for (int i = 0; i < 4; i++) {
        int r = bm + ty * 4 + i;
#pragma unroll
        for (int j = 0; j < 4; j++) {
            int c = bn + tx * 4 + j;
            out[(size_t)r * Dm + c] = acc[i][j] + bias[c] + x[(size_t)r * Dm + c];
        }
    }
}

// ---------------------------------------------------------------------------
extern "C" void kernel_launch(void* const* d_in, const int* in_sizes, int n_in,
                              void* d_out, int out_size) {
    const float* x    = (const float*)d_in[0];
    const float* uvqk = (const float*)d_in[1];
    const float* o_w  = (const float*)d_in[2];
    const float* o_b  = (const float*)d_in[3];
    const float* ts_w = (const float*)d_in[4];
    const int*   ts   = (const int*)d_in[5];
    float* out = (float*)d_out;

    float *xn, *h, *attn, *oin;
    cudaGetSymbolAddress((void**)&xn,   g_xn);
    cudaGetSymbolAddress((void**)&h,    g_h);
    cudaGetSymbolAddress((void**)&attn, g_attn);
    cudaGetSymbolAddress((void**)&oin,  g_oin);

    cudaFuncSetAttribute(attn_kernel, cudaFuncAttributeMaxDynamicSharedMemorySize,
                         ATTN_SMEM);

    ln_x_kernel<<<T_, 256>>>(x, xn);
    gemm_silu_kernel<<<dim3(16, 100), 256>>>(xn, uvqk, h);
    attn_kernel<<<dim3(32, 4, 4), 256, ATTN_SMEM>>>(h, ts, ts_w, attn);
    ln_u_kernel<<<T_, 256>>>(attn, h, oin);
    gemm_out_kernel<<<dim3(8, 100), 256>>>(oin, o_w, o_b, x, out);
}

// round 2
// speedup vs baseline: 1.5917x; 1.5917x over previous
#include <cuda_runtime.h>
#include <math.h>

// Problem constants (fixed by the reference dataset)
#define T_   6400
#define Dm   512
#define Nn   2048
#define NBUCK 128
#define INV_N (1.0f / 2048.0f)

// offsets = [0, 2048, 3584, 4608, 6400]; lengths all multiples of 64.
__constant__ int c_off[5] = {0, 2048, 3584, 4608, 6400};

// Scratch (static device globals — no allocation allowed)
__device__ float g_xn[(size_t)T_ * Dm];       // ln(x)
__device__ float g_h[(size_t)T_ * 1024];      // silu(ln(x) @ uvqk): [u|v|q|k]
__device__ float g_attn[(size_t)T_ * 256];    // attention output (jagged)
__device__ float g_oin[(size_t)T_ * 256];     // u * ln(attn)

// ---------------------------------------------------------------------------
// LayerNorm over D=512 (no affine, biased var)
// ---------------------------------------------------------------------------
__global__ __launch_bounds__(256) void ln_x_kernel(const float* __restrict__ x,
                                                   float* __restrict__ xn) {
    int t = blockIdx.x, tid = threadIdx.x;
    const float* row = x + (size_t)t * Dm;
    float v0 = row[tid], v1 = row[tid + 256];
    float s = v0 + v1, q = v0 * v0 + v1 * v1;
#pragma unroll
    for (int o = 16; o > 0; o >>= 1) {
        s += __shfl_down_sync(0xffffffffu, s, o);
        q += __shfl_down_sync(0xffffffffu, q, o);
    }
    __shared__ float rs[8], rq[8], mv[2];
    if ((tid & 31) == 0) { rs[tid >> 5] = s; rq[tid >> 5] = q; }
    __syncthreads();
    if (tid == 0) {
        float S = 0.f, Q = 0.f;
#pragma unroll
        for (int i = 0; i < 8; i++) { S += rs[i]; Q += rq[i]; }
        float m = S * (1.f / Dm);
        mv[0] = m;
        mv[1] = rsqrtf(Q * (1.f / Dm) - m * m + 1e-6f);
    }
    __syncthreads();
    float m = mv[0], r = mv[1];
    float* o = xn + (size_t)t * Dm;
    o[tid] = (v0 - m) * r;
    o[tid + 256] = (v1 - m) * r;
}

// ---------------------------------------------------------------------------
// h = silu(xn @ uvqk)   A:[6400,512] B:[512,1024] -> C:[6400,1024]
// 128x64 tile, BK=16, 256 threads, 8x4 micro-tile, float4 LDS
// ---------------------------------------------------------------------------
__global__ __launch_bounds__(256) void gemm_silu_kernel(const float* __restrict__ A,
                                                        const float* __restrict__ Bm,
                                                        float* __restrict__ C) {
    __shared__ float sA[16][132];  // sA[k][m], stride 132 (16B aligned rows)
    __shared__ float sB[16][68];   // sB[k][n]
    int bm = blockIdx.y * 128, bn = blockIdx.x * 64;
    int tid = threadIdx.x, tx = tid & 15, ty = tid >> 4;
    float acc[8][4] = {};
    for (int k0 = 0; k0 < Dm; k0 += 16) {
#pragma unroll
        for (int p = 0; p < 2; p++) {
            int l = tid + p * 256;         // 0..511 float4s
            int row = l >> 2;              // 0..127
            int c4 = (l & 3) * 4;          // 0,4,8,12
            float4 v = *reinterpret_cast<const float4*>(
                &A[(size_t)(bm + row) * Dm + k0 + c4]);
            sA[c4 + 0][row] = v.x; sA[c4 + 1][row] = v.y;
            sA[c4 + 2][row] = v.z; sA[c4 + 3][row] = v.w;
        }
        {
            int kk = tid >> 4, c4 = (tid & 15) * 4;
            *reinterpret_cast<float4*>(&sB[kk][c4]) =
                *reinterpret_cast<const float4*>(&Bm[(size_t)(k0 + kk) * 1024 + bn + c4]);
        }
        __syncthreads();
#pragma unroll
        for (int kk = 0; kk < 16; kk++) {
            float4 b4 = *reinterpret_cast<const float4*>(&sB[kk][tx * 4]);
            float4 a0 = *reinterpret_cast<const float4*>(&sA[kk][ty * 8]);
            float4 a1 = *reinterpret_cast<const float4*>(&sA[kk][ty * 8 + 4]);
            float a[8] = {a0.x, a0.y, a0.z, a0.w, a1.x, a1.y, a1.z, a1.w};
            float b[4] = {b4.x, b4.y, b4.z, b4.w};
#pragma unroll
            for (int i = 0; i < 8; i++)
#pragma unroll
                for (int j = 0; j < 4; j++) acc[i][j] = fmaf(a[i], b[j], acc[i][j]);
        }
        __syncthreads();
    }
#pragma unroll
    for (int i = 0; i < 8; i++) {
        int r = bm + ty * 8 + i;
        float4 o;
        float* s = acc[i];
        o.x = __fdividef(s[0], 1.f + __expf(-s[0]));
        o.y = __fdividef(s[1], 1.f + __expf(-s[1]));
        o.z = __fdividef(s[2], 1.f + __expf(-s[2]));
        o.w = __fdividef(s[3], 1.f + __expf(-s[3]));
        *reinterpret_cast<float4*>(&C[(size_t)r * 1024 + bn + tx * 4]) = o;
    }
}

// ---------------------------------------------------------------------------
// Jagged causal attention: 64x64 tiles, dot-product QK micro-kernel with
// XOR-swizzled smem, fast-math score phase.
// ---------------------------------------------------------------------------
#define SWZ(row) ((((row) >> 3) & 7) << 2)
#define ATTN_SMEM ((4 * 64 * 68 + 129) * 4 + 128 * 4)

__global__ __launch_bounds__(256) void attn_kernel(const float* __restrict__ h,
                                                   const int* __restrict__ ts,
                                                   const float* __restrict__ ts_w,
                                                   float* __restrict__ attn) {
    int tile = 31 - blockIdx.x;  // longest blocks first
    int b = blockIdx.y, head = blockIdx.z;
    int base = c_off[b];
    int len = c_off[b + 1] - base;
    int q0 = tile * 64;
    if (q0 >= len) return;

    extern __shared__ float sm[];
    float* sQ = sm;                 // [64][68] swizzled
    float* sK = sm + 4352;          // [64][68] swizzled
    float* sV = sm + 8704;          // [64][68] plain
    float* sS = sm + 13056;         // [key][query] swizzled
    float* sW = sm + 17408;         // 129
    int* sTq = (int*)(sm + 17537);
    int* sTk = sTq + 64;

    int tid = threadIdx.x;
    for (int i = tid; i < NBUCK + 1; i += 256) sW[i] = ts_w[i];
    if (tid < 64) sTq[tid] = ts[b * Nn + q0 + tid];

    int hofQ = 512 + head * 64, hofK = 768 + head * 64, hofV = 256 + head * 64;
    // Load Q tile (64 rows x 64 dims), swizzled
#pragma unroll
    for (int p = 0; p < 4; p++) {
        int l = tid + p * 256;
        int row = l >> 4, f4 = (l & 15) << 2;
        float4 v = *reinterpret_cast<const float4*>(
            &h[(size_t)(base + q0 + row) * 1024 + hofQ + f4]);
        *reinterpret_cast<float4*>(&sQ[row * 68 + (f4 ^ SWZ(row))]) = v;
    }

    int tx = tid & 15, ty = tid >> 4;
    int r0 = ty * 4, c0 = tx * 4;
    int qsw = SWZ(r0), ksw = SWZ(c0);
    float o[4][4] = {};

    for (int kt = 0; kt <= tile; ++kt) {
        __syncthreads();  // protect previous iteration's readers + initial loads
        int k0 = kt * 64;
        if (tid < 64) sTk[tid] = ts[b * Nn + k0 + tid];
#pragma unroll
        for (int p = 0; p < 4; p++) {
            int l = tid + p * 256;
            int row = l >> 4, f4 = (l & 15) << 2;
            size_t rowb = (size_t)(base + k0 + row) * 1024;
            float4 kv = *reinterpret_cast<const float4*>(&h[rowb + hofK + f4]);
            float4 vv = *reinterpret_cast<const float4*>(&h[rowb + hofV + f4]);
            *reinterpret_cast<float4*>(&sK[row * 68 + (f4 ^ SWZ(row))]) = kv;
            *reinterpret_cast<float4*>(&sV[row * 68 + f4]) = vv;
        }
        __syncthreads();

        // S = Q K^T : dot-product micro-kernel over float4 chunks of d
        float acc[4][4] = {};
#pragma unroll 4
        for (int kc = 0; kc < 64; kc += 4) {
            float4 q4[4], k4[4];
#pragma unroll
            for (int i = 0; i < 4; i++)
                q4[i] = *reinterpret_cast<const float4*>(&sQ[(r0 + i) * 68 + (kc ^ qsw)]);
#pragma unroll
            for (int j = 0; j < 4; j++)
                k4[j] = *reinterpret_cast<const float4*>(&sK[(c0 + j) * 68 + (kc ^ ksw)]);
#pragma unroll
            for (int i = 0; i < 4; i++)
#pragma unroll
                for (int j = 0; j < 4; j++) {
                    acc[i][j] = fmaf(q4[i].x, k4[j].x, acc[i][j]);
                    acc[i][j] = fmaf(q4[i].y, k4[j].y, acc[i][j]);
                    acc[i][j] = fmaf(q4[i].z, k4[j].z, acc[i][j]);
                    acc[i][j] = fmaf(q4[i].w, k4[j].w, acc[i][j]);
                }
        }

        // bias + silu + /N + causal mask -> sS (stored [key][query], swizzled)
        bool diag = (kt == tile);
        float sc[4][4];
#pragma unroll
        for (int i = 0; i < 4; i++) {
            int tq = sTq[r0 + i];
#pragma unroll
            for (int j = 0; j < 4; j++) {
                float ad = fabsf((float)(tq - sTk[c0 + j]));
                int bk = (int)__logf(ad + 1.0f);
                bk = bk < 0 ? 0 : (bk > NBUCK ? NBUCK : bk);
                float s = acc[i][j] + sW[bk];
                s = __fdividef(s, 1.f + __expf(-s)) * INV_N;
                if (diag && (c0 + j > r0 + i)) s = 0.f;
                sc[i][j] = s;
            }
        }
#pragma unroll
        for (int j = 0; j < 4; j++) {
            float4 v = make_float4(sc[0][j], sc[1][j], sc[2][j], sc[3][j]);
            *reinterpret_cast<float4*>(&sS[(c0 + j) * 68 + (r0 ^ ksw)]) = v;
        }
        __syncthreads();

        // O += S V  (s broadcast along queries, v contiguous along d)
#pragma unroll 4
        for (int kk = 0; kk < 64; kk++) {
            int ssw = SWZ(kk);
            float4 s4 = *reinterpret_cast<const float4*>(&sS[kk * 68 + (r0 ^ ssw)]);
            float4 v4 = *reinterpret_cast<const float4*>(&sV[kk * 68 + c0]);
            float sv[4] = {s4.x, s4.y, s4.z, s4.w};
            float vv[4] = {v4.x, v4.y, v4.z, v4.w};
#pragma unroll
            for (int i = 0; i < 4; i++)
#pragma unroll
                for (int j = 0; j < 4; j++) o[i][j] = fmaf(sv[i], vv[j], o[i][j]);
        }
    }

    // write jagged attn output (rows always < len: lengths are multiples of 64)
#pragma unroll
    for (int i = 0; i < 4; i++) {
        float4 v = make_float4(o[i][0], o[i][1], o[i][2], o[i][3]);
        *reinterpret_cast<float4*>(
            &attn[(size_t)(base + q0 + r0 + i) * 256 + head * 64 + c0]) = v;
    }
}

// ---------------------------------------------------------------------------
// o_in = u * ln(attn)   (rows of 256; u = h[:, 0:256])
// ---------------------------------------------------------------------------
__global__ __launch_bounds__(256) void ln_u_kernel(const float* __restrict__ attn,
                                                   const float* __restrict__ h,
                                                   float* __restrict__ oin) {
    int t = blockIdx.x, tid = threadIdx.x;
    float v = attn[(size_t)t * 256 + tid];
    float s = v, q = v * v;
#pragma unroll
    for (int o = 16; o > 0; o >>= 1) {
        s += __shfl_down_sync(0xffffffffu, s, o);
        q += __shfl_down_sync(0xffffffffu, q, o);
    }
    __shared__ float rs[8], rq[8], mv[2];
    if ((tid & 31) == 0) { rs[tid >> 5] = s; rq[tid >> 5] = q; }
    __syncthreads();
    if (tid == 0) {
        float S = 0.f, Q = 0.f;
#pragma unroll
        for (int i = 0; i < 8; i++) { S += rs[i]; Q += rq[i]; }
        float m = S * (1.f / 256.f);
        mv[0] = m;
        mv[1] = rsqrtf(Q * (1.f / 256.f) - m * m + 1e-6f);
    }
    __syncthreads();
    float ln = (v - mv[0]) * mv[1];
    oin[(size_t)t * 256 + tid] = h[(size_t)t * 1024 + tid] * ln;
}

// ---------------------------------------------------------------------------
// out = o_in @ o_w^T + o_b + x    A:[6400,256]  W:[512,256] (row = out-dim)
// 128x64 tile, BK=16, 8x4 micro
// ---------------------------------------------------------------------------
__global__ __launch_bounds__(256) void gemm_out_kernel(const float* __restrict__ A,
                                                       const float* __restrict__ W,
                                                       const float* __restrict__ bias,
                                                       const float* __restrict__ x,
                                                       float* __restrict__ out) {
    __shared__ float sA[16][132];
    __shared__ float sB[16][68];
    int bm = blockIdx.y * 128, bn = blockIdx.x * 64;
    int tid = threadIdx.x, tx = tid & 15, ty = tid >> 4;
    float acc[8][4] = {};
    for (int k0 = 0; k0 < 256; k0 += 16) {
#pragma unroll
        for (int p = 0; p < 2; p++) {
            int l = tid + p * 256;
            int row = l >> 2;
            int c4 = (l & 3) * 4;
            float4 v = *reinterpret_cast<const float4*>(
                &A[(size_t)(bm + row) * 256 + k0 + c4]);
            sA[c4 + 0][row] = v.x; sA[c4 + 1][row] = v.y;
            sA[c4 + 2][row] = v.z; sA[c4 + 3][row] = v.w;
        }
        {
            int c = tid >> 2, kq = (tid & 3) * 4;
            float4 w = *reinterpret_cast<const float4*>(
                &W[(size_t)(bn + c) * 256 + k0 + kq]);
            sB[kq + 0][c] = w.x; sB[kq + 1][c] = w.y;
            sB[kq + 2][c] = w.z; sB[kq + 3][c] = w.w;
        }
        __syncthreads();
#pragma unroll
        for (int kk = 0; kk < 16; kk++) {
            float4 b4 = *reinterpret_cast<const float4*>(&sB[kk][tx * 4]);
            float4 a0 = *reinterpret_cast<const float4*>(&sA[kk][ty * 8]);
            float4 a1 = *reinterpret_cast<const float4*>(&sA[kk][ty * 8 + 4]);
            float a[8] = {a0.x, a0.y, a0.z, a0.w, a1.x, a1.y, a1.z, a1.w};
            float b[4] = {b4.x, b4.y, b4.z, b4.w};
#pragma unroll
            for (int i = 0; i < 8; i++)
#pragma unroll
                for (int j = 0; j < 4; j++) acc[i][j] = fmaf(a[i], b[j], acc[i][j]);
        }
        __syncthreads();
    }
#pragma unroll
    for (int i = 0; i < 8; i++) {
        int r = bm + ty * 8 + i;
        float4 bb = *reinterpret_cast<const float4*>(&bias[bn + tx * 4]);
        float4 xx = *reinterpret_cast<const float4*>(&x[(size_t)r * Dm + bn + tx * 4]);
        float4 o;
        o.x = acc[i][0] + bb.x + xx.x;
        o.y = acc[i][1] + bb.y + xx.y;
        o.z = acc[i][2] + bb.z + xx.z;
        o.w = acc[i][3] + bb.w + xx.w;
        *reinterpret_cast<float4*>(&out[(size_t)r * Dm + bn + tx * 4]) = o;
    }
}

// ---------------------------------------------------------------------------
extern "C" void kernel_launch(void* const* d_in, const int* in_sizes, int n_in,
                              void* d_out, int out_size) {
    const float* x    = (const float*)d_in[0];
    const float* uvqk = (const float*)d_in[1];
    const float* o_w  = (const float*)d_in[2];
    const float* o_b  = (const float*)d_in[3];
    const float* ts_w = (const float*)d_in[4];
    const int*   ts   = (const int*)d_in[5];
    float* out = (float*)d_out;

    float *xn, *h, *attn, *oin;
    cudaGetSymbolAddress((void**)&xn,   g_xn);
    cudaGetSymbolAddress((void**)&h,    g_h);
    cudaGetSymbolAddress((void**)&attn, g_attn);
    cudaGetSymbolAddress((void**)&oin,  g_oin);

    cudaFuncSetAttribute(attn_kernel, cudaFuncAttributeMaxDynamicSharedMemorySize,
                         ATTN_SMEM);

    ln_x_kernel<<<T_, 256>>>(x, xn);
    gemm_silu_kernel<<<dim3(16, 50), 256>>>(xn, uvqk, h);
    attn_kernel<<<dim3(32, 4, 4), 256, ATTN_SMEM>>>(h, ts, ts_w, attn);
    ln_u_kernel<<<T_, 256>>>(attn, h, oin);
    gemm_out_kernel<<<dim3(8, 50), 256>>>(oin, o_w, o_b, x, out);
}

// round 3
// speedup vs baseline: 3.0022x; 1.8862x over previous
#include <cuda_runtime.h>
#include <math.h>

#define T_   6400
#define Dm   512
#define Nn   2048
#define NBUCK 128
#define INV_N (1.0f / 2048.0f)

// offsets = [0, 2048, 3584, 4608, 6400]; lengths all multiples of 64.
__constant__ int c_off[5] = {0, 2048, 3584, 4608, 6400};

__device__ float g_xn[(size_t)T_ * Dm];
__device__ float g_h[(size_t)T_ * 1024];
__device__ float g_attn[(size_t)T_ * 256];
__device__ float g_oin[(size_t)T_ * 256];

// ---- tf32 helpers -----------------------------------------------------------
__device__ __forceinline__ float tf32r(float x) {
    float y; asm("cvt.rna.tf32.f32 %0, %1;" : "=f"(y) : "f"(x)); return y;
}
__device__ __forceinline__ float4 tf32r4(float4 v) {
    v.x = tf32r(v.x); v.y = tf32r(v.y); v.z = tf32r(v.z); v.w = tf32r(v.w);
    return v;
}
// D += A(16x8) * B(8x8), tf32 inputs (f32 bit patterns), f32 accum
__device__ __forceinline__ void mma8(float* c, const float* a, const float* b) {
    asm volatile(
        "mma.sync.aligned.m16n8k8.row.col.f32.tf32.tf32.f32 "
        "{%0,%1,%2,%3},{%4,%5,%6,%7},{%8,%9},{%0,%1,%2,%3};"
        : "+f"(c[0]), "+f"(c[1]), "+f"(c[2]), "+f"(c[3])
        : "r"(__float_as_uint(a[0])), "r"(__float_as_uint(a[1])),
          "r"(__float_as_uint(a[2])), "r"(__float_as_uint(a[3])),
          "r"(__float_as_uint(b[0])), "r"(__float_as_uint(b[1])));
}

// ---------------------------------------------------------------------------
// LayerNorm over D=512
// ---------------------------------------------------------------------------
__global__ __launch_bounds__(256) void ln_x_kernel(const float* __restrict__ x,
                                                   float* __restrict__ xn) {
    int t = blockIdx.x, tid = threadIdx.x;
    const float* row = x + (size_t)t * Dm;
    float v0 = row[tid], v1 = row[tid + 256];
    float s = v0 + v1, q = v0 * v0 + v1 * v1;
#pragma unroll
    for (int o = 16; o > 0; o >>= 1) {
        s += __shfl_down_sync(0xffffffffu, s, o);
        q += __shfl_down_sync(0xffffffffu, q, o);
    }
    __shared__ float rs[8], rq[8], mv[2];
    if ((tid & 31) == 0) { rs[tid >> 5] = s; rq[tid >> 5] = q; }
    __syncthreads();
    if (tid == 0) {
        float S = 0.f, Q = 0.f;
#pragma unroll
        for (int i = 0; i < 8; i++) { S += rs[i]; Q += rq[i]; }
        float m = S * (1.f / Dm);
        mv[0] = m;
        mv[1] = rsqrtf(Q * (1.f / Dm) - m * m + 1e-6f);
    }
    __syncthreads();
    float m = mv[0], r = mv[1];
    float* o = xn + (size_t)t * Dm;
    o[tid] = (v0 - m) * r;
    o[tid + 256] = (v1 - m) * r;
}

// ---------------------------------------------------------------------------
// h = silu(xn @ uvqk)  [6400,512]x[512,1024] — tf32 MMA, 128x64 tile, BK=32
// ---------------------------------------------------------------------------
__global__ __launch_bounds__(256) void gemm_silu_kernel(const float* __restrict__ A,
                                                        const float* __restrict__ Bm,
                                                        float* __restrict__ C) {
    __shared__ float sA[128][36];  // [m][k], stride 36 (==4 mod 32): frag loads conflict-free
    __shared__ float sB[32][72];   // [k][n], stride 72 (==8 mod 32): frag loads conflict-free
    int bm = blockIdx.y * 128, bn = blockIdx.x * 64;
    int tid = threadIdx.x, lane = tid & 31, wid = tid >> 5;
    int g = lane >> 2, t = lane & 3;
    int wm = (wid >> 1) * 32, wn = (wid & 1) * 32;
    float acc[2][4][4] = {};
    for (int k0 = 0; k0 < Dm; k0 += 32) {
#pragma unroll
        for (int p = 0; p < 4; p++) {
            int idx = tid + p * 256;           // 1024 float4s
            int row = idx >> 3, f4 = (idx & 7) << 2;
            float4 v = tf32r4(*reinterpret_cast<const float4*>(
                &A[(size_t)(bm + row) * Dm + k0 + f4]));
            *reinterpret_cast<float4*>(&sA[row][f4]) = v;
        }
#pragma unroll
        for (int p = 0; p < 2; p++) {
            int idx = tid + p * 256;           // 512 float4s
            int row = idx >> 4, f4 = (idx & 15) << 2;
            float4 v = tf32r4(*reinterpret_cast<const float4*>(
                &Bm[(size_t)(k0 + row) * 1024 + bn + f4]));
            *reinterpret_cast<float4*>(&sB[row][f4]) = v;
        }
        __syncthreads();
#pragma unroll
        for (int kk = 0; kk < 32; kk += 8) {
            float a[2][4], bb[4][2];
#pragma unroll
            for (int i = 0; i < 2; i++) {
                int r = wm + 16 * i + g;
                a[i][0] = sA[r][kk + t];
                a[i][1] = sA[r + 8][kk + t];
                a[i][2] = sA[r][kk + t + 4];
                a[i][3] = sA[r + 8][kk + t + 4];
            }
#pragma unroll
            for (int j = 0; j < 4; j++) {
                bb[j][0] = sB[kk + t][wn + 8 * j + g];
                bb[j][1] = sB[kk + t + 4][wn + 8 * j + g];
            }
#pragma unroll
            for (int i = 0; i < 2; i++)
#pragma unroll
                for (int j = 0; j < 4; j++) mma8(acc[i][j], a[i], bb[j]);
        }
        __syncthreads();
    }
#pragma unroll
    for (int i = 0; i < 2; i++) {
        int r = bm + wm + 16 * i + g;
#pragma unroll
        for (int j = 0; j < 4; j++) {
            int c = bn + wn + 8 * j + 2 * t;
            float* s = acc[i][j];
            float2 lo, hi;
            lo.x = __fdividef(s[0], 1.f + __expf(-s[0]));
            lo.y = __fdividef(s[1], 1.f + __expf(-s[1]));
            hi.x = __fdividef(s[2], 1.f + __expf(-s[2]));
            hi.y = __fdividef(s[3], 1.f + __expf(-s[3]));
            *reinterpret_cast<float2*>(&C[(size_t)r * 1024 + c]) = lo;
            *reinterpret_cast<float2*>(&C[(size_t)(r + 8) * 1024 + c]) = hi;
        }
    }
}

// ---------------------------------------------------------------------------
// Jagged causal attention via tf32 MMA. 64x64 tiles, 8 warps (4m x 2n).
// ---------------------------------------------------------------------------
#define ATTN_SMEM ((17540 + 128) * 4)

__global__ __launch_bounds__(256) void attn_kernel(const float* __restrict__ h,
                                                   const int* __restrict__ ts,
                                                   const float* __restrict__ ts_w,
                                                   float* __restrict__ attn) {
    int tile = 31 - blockIdx.x;  // longest first
    int b = blockIdx.y, head = blockIdx.z;
    int base = c_off[b];
    int len = c_off[b + 1] - base;
    int q0 = tile * 64;
    if (q0 >= len) return;

    extern __shared__ float sm[];
    float* sQ = sm;           // [64][68]  (68 == 4 mod 32)
    float* sK = sm + 4352;    // [64][68]
    float* sV = sm + 8704;    // [64][68]
    float* sS = sm + 13056;   // [64][68]
    float* sW = sm + 17408;   // 129
    int* sTq = (int*)(sm + 17540);
    int* sTk = sTq + 64;

    int tid = threadIdx.x;
    for (int i = tid; i < NBUCK + 1; i += 256) sW[i] = ts_w[i];
    if (tid < 64) sTq[tid] = ts[b * Nn + q0 + tid];

    int hofQ = 512 + head * 64, hofK = 768 + head * 64, hofV = 256 + head * 64;
#pragma unroll
    for (int p = 0; p < 4; p++) {
        int l = tid + p * 256;
        int row = l >> 4, f4 = (l & 15) << 2;
        float4 v = tf32r4(*reinterpret_cast<const float4*>(
            &h[(size_t)(base + q0 + row) * 1024 + hofQ + f4]));
        *reinterpret_cast<float4*>(&sQ[row * 68 + f4]) = v;
    }

    int lane = tid & 31, wid = tid >> 5;
    int g = lane >> 2, t = lane & 3;
    int m0 = (wid >> 1) * 16, n0 = (wid & 1) * 32;
    float o[4][4] = {};

    for (int kt = 0; kt <= tile; ++kt) {
        __syncthreads();  // protect sK/sV/sS (and initial sQ/sTq) from prev readers
        int k0 = kt * 64;
        if (tid < 64) sTk[tid] = ts[b * Nn + k0 + tid];
#pragma unroll
        for (int p = 0; p < 4; p++) {
            int l = tid + p * 256;
            int row = l >> 4, f4 = (l & 15) << 2;
            size_t rowb = (size_t)(base + k0 + row) * 1024;
            float4 kv = tf32r4(*reinterpret_cast<const float4*>(&h[rowb + hofK + f4]));
            float4 vv = tf32r4(*reinterpret_cast<const float4*>(&h[rowb + hofV + f4]));
            *reinterpret_cast<float4*>(&sK[row * 68 + f4]) = kv;
            *reinterpret_cast<float4*>(&sV[row * 68 + f4]) = vv;
        }
        __syncthreads();

        // ---- S = Q K^T  (warp: 16x32) ----
        float s[4][4] = {};
#pragma unroll
        for (int kk = 0; kk < 64; kk += 8) {
            float a[4];
            a[0] = sQ[(m0 + g) * 68 + kk + t];
            a[1] = sQ[(m0 + g + 8) * 68 + kk + t];
            a[2] = sQ[(m0 + g) * 68 + kk + t + 4];
            a[3] = sQ[(m0 + g + 8) * 68 + kk + t + 4];
#pragma unroll
            for (int j = 0; j < 4; j++) {
                float bb[2];
                bb[0] = sK[(n0 + 8 * j + g) * 68 + kk + t];
                bb[1] = sK[(n0 + 8 * j + g) * 68 + kk + t + 4];
                mma8(s[j], a, bb);
            }
        }

        // ---- score: bias + silu + /N + causal mask; write S -> smem ----
        int tq0 = sTq[m0 + g], tq1 = sTq[m0 + g + 8];
        int qg0 = q0 + m0 + g, qg1 = qg0 + 8;
#pragma unroll
        for (int j = 0; j < 4; j++) {
            int col = n0 + 8 * j + 2 * t;
            int tk0 = sTk[col], tk1 = sTk[col + 1];
            int kg0 = k0 + col, kg1 = kg0 + 1;
            float r[4];
            int tqs[4] = {tq0, tq0, tq1, tq1};
            int tks[4] = {tk0, tk1, tk0, tk1};
            int qgs[4] = {qg0, qg0, qg1, qg1};
            int kgs[4] = {kg0, kg1, kg0, kg1};
#pragma unroll
            for (int e = 0; e < 4; e++) {
                float ad = fabsf((float)(tqs[e] - tks[e]));
                int bk = (int)__logf(ad + 1.0f);
                bk = bk < 0 ? 0 : (bk > NBUCK ? NBUCK : bk);
                float z = s[j][e] + sW[bk];
                z = __fdividef(z, 1.f + __expf(-z)) * INV_N;
                r[e] = (kgs[e] <= qgs[e]) ? z : 0.f;
            }
            *reinterpret_cast<float2*>(&sS[(m0 + g) * 68 + col]) =
                make_float2(tf32r(r[0]), tf32r(r[1]));
            *reinterpret_cast<float2*>(&sS[(m0 + g + 8) * 68 + col]) =
                make_float2(tf32r(r[2]), tf32r(r[3]));
        }
        __syncthreads();

        // ---- O += S V  (warp: 16x32 over d) ----
#pragma unroll
        for (int kk = 0; kk < 64; kk += 8) {
            float a[4];
            a[0] = sS[(m0 + g) * 68 + kk + t];
            a[1] = sS[(m0 + g + 8) * 68 + kk + t];
            a[2] = sS[(m0 + g) * 68 + kk + t + 4];
            a[3] = sS[(m0 + g + 8) * 68 + kk + t + 4];
#pragma unroll
            for (int j = 0; j < 4; j++) {
                float bb[2];
                bb[0] = sV[(kk + t) * 68 + n0 + 8 * j + g];
                bb[1] = sV[(kk + t + 4) * 68 + n0 + 8 * j + g];
                mma8(o[j], a, bb);
            }
        }
    }

#pragma unroll
    for (int j = 0; j < 4; j++) {
        int col = head * 64 + n0 + 8 * j + 2 * t;
        *reinterpret_cast<float2*>(&attn[(size_t)(base + q0 + m0 + g) * 256 + col]) =
            make_float2(o[j][0], o[j][1]);
        *reinterpret_cast<float2*>(&attn[(size_t)(base + q0 + m0 + g + 8) * 256 + col]) =
            make_float2(o[j][2], o[j][3]);
    }
}

// ---------------------------------------------------------------------------
// o_in = u * ln(attn)
// ---------------------------------------------------------------------------
__global__ __launch_bounds__(256) void ln_u_kernel(const float* __restrict__ attn,
                                                   const float* __restrict__ h,
                                                   float* __restrict__ oin) {
    int t = blockIdx.x, tid = threadIdx.x;
    float v = attn[(size_t)t * 256 + tid];
    float s = v, q = v * v;
#pragma unroll
    for (int o = 16; o > 0; o >>= 1) {
        s += __shfl_down_sync(0xffffffffu, s, o);
        q += __shfl_down_sync(0xffffffffu, q, o);
    }
    __shared__ float rs[8], rq[8], mv[2];
    if ((tid & 31) == 0) { rs[tid >> 5] = s; rq[tid >> 5] = q; }
    __syncthreads();
    if (tid == 0) {
        float S = 0.f, Q = 0.f;
#pragma unroll
        for (int i = 0; i < 8; i++) { S += rs[i]; Q += rq[i]; }
        float m = S * (1.f / 256.f);
        mv[0] = m;
        mv[1] = rsqrtf(Q * (1.f / 256.f) - m * m + 1e-6f);
    }
    __syncthreads();
    float ln = (v - mv[0]) * mv[1];
    oin[(size_t)t * 256 + tid] = h[(size_t)t * 1024 + tid] * ln;
}

// ---------------------------------------------------------------------------
// out = o_in @ o_w^T + o_b + x   [6400,256]x[512,256]^T — tf32 MMA
// ---------------------------------------------------------------------------
__global__ __launch_bounds__(256) void gemm_out_kernel(const float* __restrict__ A,
                                                       const float* __restrict__ W,
                                                       const float* __restrict__ bias,
                                                       const float* __restrict__ x,
                                                       float* __restrict__ out) {
    __shared__ float sA[128][36];
    __shared__ float sB[32][65];   // [k][n] = W[n][k]; stride 65: conflict-free transpose stores
    int bm = blockIdx.y * 128, bn = blockIdx.x * 64;
    int tid = threadIdx.x, lane = tid & 31, wid = tid >> 5;
    int g = lane >> 2, t = lane & 3;
    int wm = (wid >> 1) * 32, wn = (wid & 1) * 32;
    float acc[2][4][4] = {};
    for (int k0 = 0; k0 < 256; k0 += 32) {
#pragma unroll
        for (int p = 0; p < 4; p++) {
            int idx = tid + p * 256;
            int row = idx >> 3, f4 = (idx & 7) << 2;
            float4 v = tf32r4(*reinterpret_cast<const float4*>(
                &A[(size_t)(bm + row) * 256 + k0 + f4]));
            *reinterpret_cast<float4*>(&sA[row][f4]) = v;
        }
#pragma unroll
        for (int p = 0; p < 2; p++) {
            int idx = tid + p * 256;           // 512 float4s: 64 n-rows x 8
            int nr = idx >> 3, f4 = (idx & 7) << 2;
            float4 v = tf32r4(*reinterpret_cast<const float4*>(
                &W[(size_t)(bn + nr) * 256 + k0 + f4]));
            sB[f4 + 0][nr] = v.x; sB[f4 + 1][nr] = v.y;
            sB[f4 + 2][nr] = v.z; sB[f4 + 3][nr] = v.w;
        }
        __syncthreads();
#pragma unroll
        for (int kk = 0; kk < 32; kk += 8) {
            float a[2][4], bb[4][2];
#pragma unroll
            for (int i = 0; i < 2; i++) {
                int r = wm + 16 * i + g;
                a[i][0] = sA[r][kk + t];
                a[i][1] = sA[r + 8][kk + t];
                a[i][2] = sA[r][kk + t + 4];
                a[i][3] = sA[r + 8][kk + t + 4];
            }
#pragma unroll
            for (int j = 0; j < 4; j++) {
                bb[j][0] = sB[kk + t][wn + 8 * j + g];
                bb[j][1] = sB[kk + t + 4][wn + 8 * j + g];
            }
#pragma unroll
            for (int i = 0; i < 2; i++)
#pragma unroll
                for (int j = 0; j < 4; j++) mma8(acc[i][j], a[i], bb[j]);
        }
        __syncthreads();
    }
#pragma unroll
    for (int i = 0; i < 2; i++) {
        int r = bm + wm + 16 * i + g;
#pragma unroll
        for (int j = 0; j < 4; j++) {
            int c = bn + wn + 8 * j + 2 * t;
            float2 b2 = *reinterpret_cast<const float2*>(&bias[c]);
            float2 x0 = *reinterpret_cast<const float2*>(&x[(size_t)r * Dm + c]);
            float2 x1 = *reinterpret_cast<const float2*>(&x[(size_t)(r + 8) * Dm + c]);
            float* s = acc[i][j];
            *reinterpret_cast<float2*>(&out[(size_t)r * Dm + c]) =
                make_float2(s[0] + b2.x + x0.x, s[1] + b2.y + x0.y);
            *reinterpret_cast<float2*>(&out[(size_t)(r + 8) * Dm + c]) =
                make_float2(s[2] + b2.x + x1.x, s[3] + b2.y + x1.y);
        }
    }
}

// ---------------------------------------------------------------------------
extern "C" void kernel_launch(void* const* d_in, const int* in_sizes, int n_in,
                              void* d_out, int out_size) {
    const float* x    = (const float*)d_in[0];
    const float* uvqk = (const float*)d_in[1];
    const float* o_w  = (const float*)d_in[2];
    const float* o_b  = (const float*)d_in[3];
    const float* ts_w = (const float*)d_in[4];
    const int*   ts   = (const int*)d_in[5];
    float* out = (float*)d_out;

    float *xn, *h, *attn, *oin;
    cudaGetSymbolAddress((void**)&xn,   g_xn);
    cudaGetSymbolAddress((void**)&h,    g_h);
    cudaGetSymbolAddress((void**)&attn, g_attn);
    cudaGetSymbolAddress((void**)&oin,  g_oin);

    cudaFuncSetAttribute(attn_kernel, cudaFuncAttributeMaxDynamicSharedMemorySize,
                         ATTN_SMEM);

    ln_x_kernel<<<T_, 256>>>(x, xn);
    gemm_silu_kernel<<<dim3(16, 50), 256>>>(xn, uvqk, h);
    attn_kernel<<<dim3(32, 4, 4), 256, ATTN_SMEM>>>(h, ts, ts_w, attn);
    ln_u_kernel<<<T_, 256>>>(attn, h, oin);
    gemm_out_kernel<<<dim3(8, 50), 256>>>(oin, o_w, o_b, x, out);
}

// round 4
// speedup vs baseline: 4.0448x; 1.3473x over previous
#include <cuda_runtime.h>
#include <math.h>
#include <stdint.h>

#define T_   6400
#define Dm   512
#define Nn   2048
#define NBUCK 128
#define INV_N (1.0f / 2048.0f)

// offsets = [0, 2048, 3584, 4608, 6400]; lengths all multiples of 64.
__constant__ int c_off[5] = {0, 2048, 3584, 4608, 6400};

__device__ float g_xn[(size_t)T_ * Dm];
__device__ float g_uvqkr[(size_t)Dm * 1024];
__device__ float g_h[(size_t)T_ * 1024];
__device__ float g_attn[(size_t)T_ * 256];
__device__ float g_oin[(size_t)T_ * 256];

// ---- tf32 / mma / cp.async helpers ----------------------------------------
__device__ __forceinline__ float tf32r(float x) {
    float y; asm("cvt.rna.tf32.f32 %0, %1;" : "=f"(y) : "f"(x)); return y;
}
__device__ __forceinline__ float4 tf32r4(float4 v) {
    v.x = tf32r(v.x); v.y = tf32r(v.y); v.z = tf32r(v.z); v.w = tf32r(v.w);
    return v;
}
__device__ __forceinline__ void mma8(float* c, const float* a, const float* b) {
    asm volatile(
        "mma.sync.aligned.m16n8k8.row.col.f32.tf32.tf32.f32 "
        "{%0,%1,%2,%3},{%4,%5,%6,%7},{%8,%9},{%0,%1,%2,%3};"
        : "+f"(c[0]), "+f"(c[1]), "+f"(c[2]), "+f"(c[3])
        : "r"(__float_as_uint(a[0])), "r"(__float_as_uint(a[1])),
          "r"(__float_as_uint(a[2])), "r"(__float_as_uint(a[3])),
          "r"(__float_as_uint(b[0])), "r"(__float_as_uint(b[1])));
}
__device__ __forceinline__ void cpa16(void* dst, const void* src) {
    uint32_t d = (uint32_t)__cvta_generic_to_shared(dst);
    asm volatile("cp.async.cg.shared.global [%0], [%1], 16;" :: "r"(d), "l"(src));
}
__device__ __forceinline__ void cpa_commit() { asm volatile("cp.async.commit_group;"); }
__device__ __forceinline__ void cpa_wait0()  { asm volatile("cp.async.wait_group 0;"); }

// ---------------------------------------------------------------------------
// tf32 pre-round of uvqk
// ---------------------------------------------------------------------------
__global__ __launch_bounds__(256) void cvt_tf32_kernel(const float4* __restrict__ in,
                                                       float4* __restrict__ out) {
    int i = blockIdx.x * 256 + threadIdx.x;
    out[i] = tf32r4(in[i]);
}

// ---------------------------------------------------------------------------
// LayerNorm over D=512, warp-per-row, tf32-rounded output
// ---------------------------------------------------------------------------
__global__ __launch_bounds__(256) void ln_x_kernel(const float* __restrict__ x,
                                                   float* __restrict__ xn) {
    int row = blockIdx.x * 8 + (threadIdx.x >> 5);
    int lane = threadIdx.x & 31;
    const float* r = x + (size_t)row * Dm;
    float4 v[4];
    float s = 0.f, q = 0.f;
#pragma unroll
    for (int i = 0; i < 4; i++) {
        v[i] = *reinterpret_cast<const float4*>(&r[lane * 4 + i * 128]);
        s += v[i].x + v[i].y + v[i].z + v[i].w;
        q += v[i].x * v[i].x + v[i].y * v[i].y + v[i].z * v[i].z + v[i].w * v[i].w;
    }
#pragma unroll
    for (int o = 16; o > 0; o >>= 1) {
        s += __shfl_xor_sync(0xffffffffu, s, o);
        q += __shfl_xor_sync(0xffffffffu, q, o);
    }
    float m = s * (1.f / Dm);
    float rstd = rsqrtf(q * (1.f / Dm) - m * m + 1e-6f);
    float* ov = xn + (size_t)row * Dm;
#pragma unroll
    for (int i = 0; i < 4; i++) {
        float4 w;
        w.x = tf32r((v[i].x - m) * rstd); w.y = tf32r((v[i].y - m) * rstd);
        w.z = tf32r((v[i].z - m) * rstd); w.w = tf32r((v[i].w - m) * rstd);
        *reinterpret_cast<float4*>(&ov[lane * 4 + i * 128]) = w;
    }
}

// ---------------------------------------------------------------------------
// h = silu(xn @ uvqkr)  tf32 MMA, 128x64 tile, BK=32, cp.async double buffer
// ---------------------------------------------------------------------------
#define G1_SMEM ((2 * (128 * 36 + 32 * 72)) * 4)

__global__ __launch_bounds__(256) void gemm_silu_kernel(const float* __restrict__ A,
                                                        const float* __restrict__ Bm,
                                                        float* __restrict__ C) {
    extern __shared__ float sm[];
    float* sA = sm;            // [2][128][36]
    float* sB = sm + 9216;     // [2][32][72]
    int bm = blockIdx.y * 128, bn = blockIdx.x * 64;
    int tid = threadIdx.x, lane = tid & 31, wid = tid >> 5;
    int g = lane >> 2, t = lane & 3;
    int wm = (wid >> 1) * 32, wn = (wid & 1) * 32;

    auto pf = [&](int k0, int buf) {
        float* dA = sA + buf * 4608;
        float* dB = sB + buf * 2304;
#pragma unroll
        for (int p = 0; p < 4; p++) {
            int idx = tid + p * 256;
            int row = idx >> 3, f4 = (idx & 7) << 2;
            cpa16(&dA[row * 36 + f4], &A[(size_t)(bm + row) * Dm + k0 + f4]);
        }
#pragma unroll
        for (int p = 0; p < 2; p++) {
            int idx = tid + p * 256;
            int row = idx >> 4, f4 = (idx & 15) << 2;
            cpa16(&dB[row * 72 + f4], &Bm[(size_t)(k0 + row) * 1024 + bn + f4]);
        }
        cpa_commit();
    };

    float acc[2][4][4] = {};
    pf(0, 0);
    for (int it = 0; it < 16; it++) {
        cpa_wait0();
        __syncthreads();
        if (it + 1 < 16) pf((it + 1) * 32, (it + 1) & 1);
        float* cA = sA + (it & 1) * 4608;
        float* cB = sB + (it & 1) * 2304;
#pragma unroll
        for (int kk = 0; kk < 32; kk += 8) {
            float a[2][4], bb[4][2];
#pragma unroll
            for (int i = 0; i < 2; i++) {
                int r = wm + 16 * i + g;
                a[i][0] = cA[r * 36 + kk + t];
                a[i][1] = cA[(r + 8) * 36 + kk + t];
                a[i][2] = cA[r * 36 + kk + t + 4];
                a[i][3] = cA[(r + 8) * 36 + kk + t + 4];
            }
#pragma unroll
            for (int j = 0; j < 4; j++) {
                bb[j][0] = cB[(kk + t) * 72 + wn + 8 * j + g];
                bb[j][1] = cB[(kk + t + 4) * 72 + wn + 8 * j + g];
            }
#pragma unroll
            for (int i = 0; i < 2; i++)
#pragma unroll
                for (int j = 0; j < 4; j++) mma8(acc[i][j], a[i], bb[j]);
        }
        __syncthreads();
    }
#pragma unroll
    for (int i = 0; i < 2; i++) {
        int r = bm + wm + 16 * i + g;
#pragma unroll
        for (int j = 0; j < 4; j++) {
            int c = bn + wn + 8 * j + 2 * t;
            float* s = acc[i][j];
            float2 lo, hi;
            lo.x = tf32r(__fdividef(s[0], 1.f + __expf(-s[0])));
            lo.y = tf32r(__fdividef(s[1], 1.f + __expf(-s[1])));
            hi.x = tf32r(__fdividef(s[2], 1.f + __expf(-s[2])));
            hi.y = tf32r(__fdividef(s[3], 1.f + __expf(-s[3])));
            *reinterpret_cast<float2*>(&C[(size_t)r * 1024 + c]) = lo;
            *reinterpret_cast<float2*>(&C[(size_t)(r + 8) * 1024 + c]) = hi;
        }
    }
}

// ---------------------------------------------------------------------------
// Split-K jagged causal attention. Work unit = (b, qtile, chunk of <=8 ktiles).
// Outputs accumulated with atomicAdd into pre-zeroed g_attn.
// ---------------------------------------------------------------------------
#define ATTN_SMEM (26433 * 4)

__global__ __launch_bounds__(256) void attn_kernel(const float* __restrict__ h,
                                                   const int* __restrict__ ts,
                                                   const float* __restrict__ ts_w,
                                                   float* __restrict__ attn) {
    // decode unit -> (b, tile, chunk); chunks(t) = (t>>3)+1, tiles descending
    int u = blockIdx.x;
    int b;
    if (u < 80) { b = 0; }
    else if (u < 128) { b = 1; u -= 80; }
    else if (u < 152) { b = 2; u -= 128; }
    else { b = 3; u -= 152; }
    int base = c_off[b];
    int Tb = (c_off[b + 1] - base) >> 6;
    int tile = 0, chunk = 0;
    for (int tt = Tb - 1; tt >= 0; --tt) {
        int c = (tt >> 3) + 1;
        if (u < c) { tile = tt; chunk = u; break; }
        u -= c;
    }
    int head = blockIdx.y;
    int q0 = tile * 64;
    int kt0 = chunk * 8;
    int nkt = min(kt0 + 8, tile + 1) - kt0;

    extern __shared__ float sm[];
    float* sQ = sm;              // [64][68]
    float* sKb = sm + 4352;      // [2][64][68]
    float* sVb = sm + 13056;     // [2][64][68]
    float* sS = sm + 21760;      // [64][68]
    float* sW = sm + 26112;      // 129
    int* sTq = (int*)(sm + 26241);
    int* sTk = (int*)(sm + 26305);  // [2][64]

    int tid = threadIdx.x;
    int hofQ = 512 + head * 64, hofK = 768 + head * 64, hofV = 256 + head * 64;

    auto pfKV = [&](int kt, int buf) {
        int k0 = kt * 64;
        if (tid < 64) sTk[buf * 64 + tid] = ts[b * Nn + k0 + tid];
        float* dK = sKb + buf * 4352;
        float* dV = sVb + buf * 4352;
#pragma unroll
        for (int p = 0; p < 4; p++) {
            int l = tid + p * 256;
            int row = l >> 4, f4 = (l & 15) << 2;
            const float* src = &h[(size_t)(base + k0 + row) * 1024];
            cpa16(&dK[row * 68 + f4], src + hofK + f4);
            cpa16(&dV[row * 68 + f4], src + hofV + f4);
        }
    };

    if (tid < 129) sW[tid] = ts_w[tid];
    if (tid < 64) sTq[tid] = ts[b * Nn + q0 + tid];
#pragma unroll
    for (int p = 0; p < 4; p++) {
        int l = tid + p * 256;
        int row = l >> 4, f4 = (l & 15) << 2;
        cpa16(&sQ[row * 68 + f4], &h[(size_t)(base + q0 + row) * 1024 + hofQ + f4]);
    }
    pfKV(kt0, 0);
    cpa_commit();

    int lane = tid & 31, wid = tid >> 5;
    int g = lane >> 2, t = lane & 3;
    int m0 = (wid >> 1) * 16, n0 = (wid & 1) * 32;
    int mgrp = wid >> 1;
    float o[4][4] = {};

    for (int ii = 0; ii < nkt; ii++) {
        int kt = kt0 + ii;
        int buf = ii & 1;
        cpa_wait0();
        __syncthreads();
        if (ii + 1 < nkt) { pfKV(kt + 1, buf ^ 1); cpa_commit(); }

        float* sK = sKb + buf * 4352;
        float* sV = sVb + buf * 4352;
        int* sTkb = sTk + buf * 64;
        int k0 = kt * 64;

        // ---- S = Q K^T ----
        float s4[4][4] = {};
#pragma unroll
        for (int kk = 0; kk < 64; kk += 8) {
            float a[4];
            a[0] = sQ[(m0 + g) * 68 + kk + t];
            a[1] = sQ[(m0 + g + 8) * 68 + kk + t];
            a[2] = sQ[(m0 + g) * 68 + kk + t + 4];
            a[3] = sQ[(m0 + g + 8) * 68 + kk + t + 4];
#pragma unroll
            for (int j = 0; j < 4; j++) {
                float bb[2];
                bb[0] = sK[(n0 + 8 * j + g) * 68 + kk + t];
                bb[1] = sK[(n0 + 8 * j + g) * 68 + kk + t + 4];
                mma8(s4[j], a, bb);
            }
        }

        // ---- score: bias + silu + /N + causal ----
        int tq0 = sTq[m0 + g], tq1 = sTq[m0 + g + 8];
        int qg0 = q0 + m0 + g, qg1 = qg0 + 8;
#pragma unroll
        for (int j = 0; j < 4; j++) {
            int col = n0 + 8 * j + 2 * t;
            int tk0 = sTkb[col], tk1 = sTkb[col + 1];
            int kg0 = k0 + col, kg1 = kg0 + 1;
            float r[4];
            int tqs[4] = {tq0, tq0, tq1, tq1};
            int tks[4] = {tk0, tk1, tk0, tk1};
            int qgs[4] = {qg0, qg0, qg1, qg1};
            int kgs[4] = {kg0, kg1, kg0, kg1};
#pragma unroll
            for (int e = 0; e < 4; e++) {
                float ad = fabsf((float)(tqs[e] - tks[e]));
                int bk = (int)__logf(ad + 1.0f);
                bk = bk < 0 ? 0 : (bk > NBUCK ? NBUCK : bk);
                float z = s4[j][e] + sW[bk];
                z = __fdividef(z, 1.f + __expf(-z)) * INV_N;
                r[e] = (kgs[e] <= qgs[e]) ? z : 0.f;
            }
            *reinterpret_cast<float2*>(&sS[(m0 + g) * 68 + col]) =
                make_float2(tf32r(r[0]), tf32r(r[1]));
            *reinterpret_cast<float2*>(&sS[(m0 + g + 8) * 68 + col]) =
                make_float2(tf32r(r[2]), tf32r(r[3]));
        }
        // only the two warps sharing this m-row group must sync before SV
        asm volatile("bar.sync %0, 64;" :: "r"(1 + mgrp));

        // ---- O += S V ----
#pragma unroll
        for (int kk = 0; kk < 64; kk += 8) {
            float a[4];
            a[0] = sS[(m0 + g) * 68 + kk + t];
            a[1] = sS[(m0 + g + 8) * 68 + kk + t];
            a[2] = sS[(m0 + g) * 68 + kk + t + 4];
            a[3] = sS[(m0 + g + 8) * 68 + kk + t + 4];
#pragma unroll
            for (int j = 0; j < 4; j++) {
                float bb[2];
                bb[0] = sV[(kk + t) * 68 + n0 + 8 * j + g];
                bb[1] = sV[(kk + t + 4) * 68 + n0 + 8 * j + g];
                mma8(o[j], a, bb);
            }
        }
    }

    // accumulate into g_attn
#pragma unroll
    for (int j = 0; j < 4; j++) {
        int col = head * 64 + n0 + 8 * j + 2 * t;
        float* p0 = &attn[(size_t)(base + q0 + m0 + g) * 256 + col];
        float* p1 = &attn[(size_t)(base + q0 + m0 + g + 8) * 256 + col];
        atomicAdd(p0, o[j][0]);
        atomicAdd(p0 + 1, o[j][1]);
        atomicAdd(p1, o[j][2]);
        atomicAdd(p1 + 1, o[j][3]);
    }
}

// ---------------------------------------------------------------------------
// o_in = tf32r(u * ln(attn)), warp-per-row
// ---------------------------------------------------------------------------
__global__ __launch_bounds__(256) void ln_u_kernel(const float* __restrict__ attn,
                                                   const float* __restrict__ h,
                                                   float* __restrict__ oin) {
    int row = blockIdx.x * 8 + (threadIdx.x >> 5);
    int lane = threadIdx.x & 31;
    const float* r = attn + (size_t)row * 256;
    float4 v[2];
    float s = 0.f, q = 0.f;
#pragma unroll
    for (int i = 0; i < 2; i++) {
        v[i] = *reinterpret_cast<const float4*>(&r[lane * 4 + i * 128]);
        s += v[i].x + v[i].y + v[i].z + v[i].w;
        q += v[i].x * v[i].x + v[i].y * v[i].y + v[i].z * v[i].z + v[i].w * v[i].w;
    }
#pragma unroll
    for (int o = 16; o > 0; o >>= 1) {
        s += __shfl_xor_sync(0xffffffffu, s, o);
        q += __shfl_xor_sync(0xffffffffu, q, o);
    }
    float m = s * (1.f / 256.f);
    float rstd = rsqrtf(q * (1.f / 256.f) - m * m + 1e-6f);
    float* ov = oin + (size_t)row * 256;
#pragma unroll
    for (int i = 0; i < 2; i++) {
        float4 u4 = *reinterpret_cast<const float4*>(
            &h[(size_t)row * 1024 + lane * 4 + i * 128]);
        float4 w;
        w.x = tf32r(u4.x * (v[i].x - m) * rstd);
        w.y = tf32r(u4.y * (v[i].y - m) * rstd);
        w.z = tf32r(u4.z * (v[i].z - m) * rstd);
        w.w = tf32r(u4.w * (v[i].w - m) * rstd);
        *reinterpret_cast<float4*>(&ov[lane * 4 + i * 128]) = w;
    }
}

// ---------------------------------------------------------------------------
// out = o_in @ o_w^T + o_b + x    tf32 MMA, 128x64 tile
// ---------------------------------------------------------------------------
__global__ __launch_bounds__(256) void gemm_out_kernel(const float* __restrict__ A,
                                                       const float* __restrict__ W,
                                                       const float* __restrict__ bias,
                                                       const float* __restrict__ x,
                                                       float* __restrict__ out) {
    __shared__ float sA[128][36];
    __shared__ float sB[32][65];
    int bm = blockIdx.y * 128, bn = blockIdx.x * 64;
    int tid = threadIdx.x, lane = tid & 31, wid = tid >> 5;
    int g = lane >> 2, t = lane & 3;
    int wm = (wid >> 1) * 32, wn = (wid & 1) * 32;
    float acc[2][4][4] = {};
    for (int k0 = 0; k0 < 256; k0 += 32) {
#pragma unroll
        for (int p = 0; p < 4; p++) {
            int idx = tid + p * 256;
            int row = idx >> 3, f4 = (idx & 7) << 2;
            float4 v = *reinterpret_cast<const float4*>(
                &A[(size_t)(bm + row) * 256 + k0 + f4]);
            *reinterpret_cast<float4*>(&sA[row][f4]) = v;
        }
#pragma unroll
        for (int p = 0; p < 2; p++) {
            int idx = tid + p * 256;
            int nr = idx >> 3, f4 = (idx & 7) << 2;
            float4 v = tf32r4(*reinterpret_cast<const float4*>(
                &W[(size_t)(bn + nr) * 256 + k0 + f4]));
            sB[f4 + 0][nr] = v.x; sB[f4 + 1][nr] = v.y;
            sB[f4 + 2][nr] = v.z; sB[f4 + 3][nr] = v.w;
        }
        __syncthreads();
#pragma unroll
        for (int kk = 0; kk < 32; kk += 8) {
            float a[2][4], bb[4][2];
#pragma unroll
            for (int i = 0; i < 2; i++) {
                int r = wm + 16 * i + g;
                a[i][0] = sA[r][kk + t];
                a[i][1] = sA[r + 8][kk + t];
                a[i][2] = sA[r][kk + t + 4];
                a[i][3] = sA[r + 8][kk + t + 4];
            }
#pragma unroll
            for (int j = 0; j < 4; j++) {
                bb[j][0] = sB[kk + t][wn + 8 * j + g];
                bb[j][1] = sB[kk + t + 4][wn + 8 * j + g];
            }
#pragma unroll
            for (int i = 0; i < 2; i++)
#pragma unroll
                for (int j = 0; j < 4; j++) mma8(acc[i][j], a[i], bb[j]);
        }
        __syncthreads();
    }
#pragma unroll
    for (int i = 0; i < 2; i++) {
        int r = bm + wm + 16 * i + g;
#pragma unroll
        for (int j = 0; j < 4; j++) {
            int c = bn + wn + 8 * j + 2 * t;
            float2 b2 = *reinterpret_cast<const float2*>(&bias[c]);
            float2 x0 = *reinterpret_cast<const float2*>(&x[(size_t)r * Dm + c]);
            float2 x1 = *reinterpret_cast<const float2*>(&x[(size_t)(r + 8) * Dm + c]);
            float* s = acc[i][j];
            *reinterpret_cast<float2*>(&out[(size_t)r * Dm + c]) =
                make_float2(s[0] + b2.x + x0.x, s[1] + b2.y + x0.y);
            *reinterpret_cast<float2*>(&out[(size_t)(r + 8) * Dm + c]) =
                make_float2(s[2] + b2.x + x1.x, s[3] + b2.y + x1.y);
        }
    }
}

// ---------------------------------------------------------------------------
extern "C" void kernel_launch(void* const* d_in, const int* in_sizes, int n_in,
                              void* d_out, int out_size) {
    const float* x    = (const float*)d_in[0];
    const float* uvqk = (const float*)d_in[1];
    const float* o_w  = (const float*)d_in[2];
    const float* o_b  = (const float*)d_in[3];
    const float* ts_w = (const float*)d_in[4];
    const int*   ts   = (const int*)d_in[5];
    float* out = (float*)d_out;

    float *xn, *uvqkr, *h, *attn, *oin;
    cudaGetSymbolAddress((void**)&xn,    g_xn);
    cudaGetSymbolAddress((void**)&uvqkr, g_uvqkr);
    cudaGetSymbolAddress((void**)&h,     g_h);
    cudaGetSymbolAddress((void**)&attn,  g_attn);
    cudaGetSymbolAddress((void**)&oin,   g_oin);

    cudaFuncSetAttribute(attn_kernel, cudaFuncAttributeMaxDynamicSharedMemorySize,
                         ATTN_SMEM);
    cudaFuncSetAttribute(gemm_silu_kernel, cudaFuncAttributeMaxDynamicSharedMemorySize,
                         G1_SMEM);

    cudaMemsetAsync(attn, 0, (size_t)T_ * 256 * sizeof(float));
    ln_x_kernel<<<800, 256>>>(x, xn);
    cvt_tf32_kernel<<<512, 256>>>((const float4*)uvqk, (float4*)uvqkr);
    gemm_silu_kernel<<<dim3(16, 50), 256, G1_SMEM>>>(xn, uvqkr, h);
    attn_kernel<<<dim3(216, 4), 256, ATTN_SMEM>>>(h, ts, ts_w, attn);
    ln_u_kernel<<<800, 256>>>(attn, h, oin);
    gemm_out_kernel<<<dim3(8, 50), 256>>>(oin, o_w, o_b, x, out);
}

// round 5
// speedup vs baseline: 4.2655x; 1.0545x over previous
#include <cuda_runtime.h>
#include <math.h>
#include <stdint.h>

#define T_   6400
#define Dm   512
#define Nn   2048
#define NBUCK 128
#define INV_N (1.0f / 2048.0f)

// offsets = [0, 2048, 3584, 4608, 6400]; lengths all multiples of 64.
__constant__ int c_off[5] = {0, 2048, 3584, 4608, 6400};

__device__ float g_xn[(size_t)T_ * Dm];
__device__ float g_uvqkr[(size_t)Dm * 1024];
__device__ float g_h[(size_t)T_ * 1024];
__device__ float g_attn[(size_t)T_ * 256];
__device__ float g_oin[(size_t)T_ * 256];

// ---- tf32 / mma / cp.async helpers ----------------------------------------
__device__ __forceinline__ float tf32r(float x) {
    float y; asm("cvt.rna.tf32.f32 %0, %1;" : "=f"(y) : "f"(x)); return y;
}
__device__ __forceinline__ float4 tf32r4(float4 v) {
    v.x = tf32r(v.x); v.y = tf32r(v.y); v.z = tf32r(v.z); v.w = tf32r(v.w);
    return v;
}
__device__ __forceinline__ void mma8(float* c, const float* a, const float* b) {
    asm volatile(
        "mma.sync.aligned.m16n8k8.row.col.f32.tf32.tf32.f32 "
        "{%0,%1,%2,%3},{%4,%5,%6,%7},{%8,%9},{%0,%1,%2,%3};"
        : "+f"(c[0]), "+f"(c[1]), "+f"(c[2]), "+f"(c[3])
        : "r"(__float_as_uint(a[0])), "r"(__float_as_uint(a[1])),
          "r"(__float_as_uint(a[2])), "r"(__float_as_uint(a[3])),
          "r"(__float_as_uint(b[0])), "r"(__float_as_uint(b[1])));
}
__device__ __forceinline__ void cpa16(void* dst, const void* src) {
    uint32_t d = (uint32_t)__cvta_generic_to_shared(dst);
    asm volatile("cp.async.cg.shared.global [%0], [%1], 16;" :: "r"(d), "l"(src));
}
__device__ __forceinline__ void cpa_commit() { asm volatile("cp.async.commit_group;"); }
__device__ __forceinline__ void cpa_wait0()  { asm volatile("cp.async.wait_group 0;"); }

// ---------------------------------------------------------------------------
// tf32 pre-round of uvqk
// ---------------------------------------------------------------------------
__global__ __launch_bounds__(256) void cvt_tf32_kernel(const float4* __restrict__ in,
                                                       float4* __restrict__ out) {
    int i = blockIdx.x * 256 + threadIdx.x;
    out[i] = tf32r4(in[i]);
}

// ---------------------------------------------------------------------------
// LayerNorm over D=512, warp-per-row, tf32-rounded output
// ---------------------------------------------------------------------------
__global__ __launch_bounds__(256) void ln_x_kernel(const float* __restrict__ x,
                                                   float* __restrict__ xn) {
    int row = blockIdx.x * 8 + (threadIdx.x >> 5);
    int lane = threadIdx.x & 31;
    const float* r = x + (size_t)row * Dm;
    float4 v[4];
    float s = 0.f, q = 0.f;
#pragma unroll
    for (int i = 0; i < 4; i++) {
        v[i] = *reinterpret_cast<const float4*>(&r[lane * 4 + i * 128]);
        s += v[i].x + v[i].y + v[i].z + v[i].w;
        q += v[i].x * v[i].x + v[i].y * v[i].y + v[i].z * v[i].z + v[i].w * v[i].w;
    }
#pragma unroll
    for (int o = 16; o > 0; o >>= 1) {
        s += __shfl_xor_sync(0xffffffffu, s, o);
        q += __shfl_xor_sync(0xffffffffu, q, o);
    }
    float m = s * (1.f / Dm);
    float rstd = rsqrtf(q * (1.f / Dm) - m * m + 1e-6f);
    float* ov = xn + (size_t)row * Dm;
#pragma unroll
    for (int i = 0; i < 4; i++) {
        float4 w;
        w.x = tf32r((v[i].x - m) * rstd); w.y = tf32r((v[i].y - m) * rstd);
        w.z = tf32r((v[i].z - m) * rstd); w.w = tf32r((v[i].w - m) * rstd);
        *reinterpret_cast<float4*>(&ov[lane * 4 + i * 128]) = w;
    }
}

// ---------------------------------------------------------------------------
// h = silu(xn @ uvqkr)  tf32 MMA, 128x64 tile, BK=32, cp.async double buffer.
// q/k sections (cols >= 512) stored with per-8-col interleave permutation
// alpha: c<4 -> 2c ; c>=4 -> 2(c-4)+1  (so attention reads pair (t,t+4) as
// one float2). Thread's C-frag pair (2t,2t+1) maps to (p0, p0+2).
// ---------------------------------------------------------------------------
#define G1_SMEM ((2 * (128 * 36 + 32 * 72)) * 4)

__global__ __launch_bounds__(256) void gemm_silu_kernel(const float* __restrict__ A,
                                                        const float* __restrict__ Bm,
                                                        float* __restrict__ C) {
    extern __shared__ float sm[];
    float* sA = sm;            // [2][128][36]
    float* sB = sm + 9216;     // [2][32][72]
    int bm = blockIdx.y * 128, bn = blockIdx.x * 64;
    int tid = threadIdx.x, lane = tid & 31, wid = tid >> 5;
    int g = lane >> 2, t = lane & 3;
    int wm = (wid >> 1) * 32, wn = (wid & 1) * 32;

    auto pf = [&](int k0, int buf) {
        float* dA = sA + buf * 4608;
        float* dB = sB + buf * 2304;
#pragma unroll
        for (int p = 0; p < 4; p++) {
            int idx = tid + p * 256;
            int row = idx >> 3, f4 = (idx & 7) << 2;
            cpa16(&dA[row * 36 + f4], &A[(size_t)(bm + row) * Dm + k0 + f4]);
        }
#pragma unroll
        for (int p = 0; p < 2; p++) {
            int idx = tid + p * 256;
            int row = idx >> 4, f4 = (idx & 15) << 2;
            cpa16(&dB[row * 72 + f4], &Bm[(size_t)(k0 + row) * 1024 + bn + f4]);
        }
        cpa_commit();
    };

    float acc[2][4][4] = {};
    pf(0, 0);
    for (int it = 0; it < 16; it++) {
        cpa_wait0();
        __syncthreads();
        if (it + 1 < 16) pf((it + 1) * 32, (it + 1) & 1);
        float* cA = sA + (it & 1) * 4608;
        float* cB = sB + (it & 1) * 2304;
#pragma unroll
        for (int kk = 0; kk < 32; kk += 8) {
            float a[2][4], bb[4][2];
#pragma unroll
            for (int i = 0; i < 2; i++) {
                int r = wm + 16 * i + g;
                a[i][0] = cA[r * 36 + kk + t];
                a[i][1] = cA[(r + 8) * 36 + kk + t];
                a[i][2] = cA[r * 36 + kk + t + 4];
                a[i][3] = cA[(r + 8) * 36 + kk + t + 4];
            }
#pragma unroll
            for (int j = 0; j < 4; j++) {
                bb[j][0] = cB[(kk + t) * 72 + wn + 8 * j + g];
                bb[j][1] = cB[(kk + t + 4) * 72 + wn + 8 * j + g];
            }
#pragma unroll
            for (int i = 0; i < 2; i++)
#pragma unroll
                for (int j = 0; j < 4; j++) mma8(acc[i][j], a[i], bb[j]);
        }
        __syncthreads();
    }
    bool perm = (bn >= 512);
    int p0 = (t < 2) ? 4 * t : 4 * t - 7;
#pragma unroll
    for (int i = 0; i < 2; i++) {
        int r = bm + wm + 16 * i + g;
#pragma unroll
        for (int j = 0; j < 4; j++) {
            float* s = acc[i][j];
            float e0 = tf32r(__fdividef(s[0], 1.f + __expf(-s[0])));
            float e1 = tf32r(__fdividef(s[1], 1.f + __expf(-s[1])));
            float e2 = tf32r(__fdividef(s[2], 1.f + __expf(-s[2])));
            float e3 = tf32r(__fdividef(s[3], 1.f + __expf(-s[3])));
            if (!perm) {
                int c = bn + wn + 8 * j + 2 * t;
                *reinterpret_cast<float2*>(&C[(size_t)r * 1024 + c]) = make_float2(e0, e1);
                *reinterpret_cast<float2*>(&C[(size_t)(r + 8) * 1024 + c]) = make_float2(e2, e3);
            } else {
                int cb = bn + wn + 8 * j;
                C[(size_t)r * 1024 + cb + p0] = e0;
                C[(size_t)r * 1024 + cb + p0 + 2] = e1;
                C[(size_t)(r + 8) * 1024 + cb + p0] = e2;
                C[(size_t)(r + 8) * 1024 + cb + p0 + 2] = e3;
            }
        }
    }
}

// ---------------------------------------------------------------------------
// Split-K jagged causal attention.
// Q fragments hoisted to registers; sQ space reused for S.
// K/Q/S stride 72 (conflict-free .64), V stride 68.
// V rows permuted per-8 (key 2t -> row t, key 2t+1 -> row t+4) so S->A frags
// are float2-loadable while S writes stay float2.
// ---------------------------------------------------------------------------
#define ATTN_SMEM (22849 * 4)

__global__ __launch_bounds__(256) void attn_kernel(const float* __restrict__ h,
                                                   const int* __restrict__ ts,
                                                   const float* __restrict__ ts_w,
                                                   float* __restrict__ attn) {
    // decode unit -> (b, tile, chunk); chunks(t) = (t>>3)+1, tiles descending
    int u = blockIdx.x;
    int b;
    if (u < 80) { b = 0; }
    else if (u < 128) { b = 1; u -= 80; }
    else if (u < 152) { b = 2; u -= 128; }
    else { b = 3; u -= 152; }
    int base = c_off[b];
    int Tb = (c_off[b + 1] - base) >> 6;
    int tile = 0, chunk = 0;
    for (int tt = Tb - 1; tt >= 0; --tt) {
        int c = (tt >> 3) + 1;
        if (u < c) { tile = tt; chunk = u; break; }
        u -= c;
    }
    int head = blockIdx.y;
    int q0 = tile * 64;
    int kt0 = chunk * 8;
    int nkt = min(kt0 + 8, tile + 1) - kt0;

    extern __shared__ float sm[];
    float* sQS = sm;                // [64][72]: Q during init, then S
    float* sKb = sm + 4608;         // [2][64][72]
    float* sVb = sm + 13824;        // [2][64][68] (rows permuted)
    float* sW  = sm + 22528;        // 129
    int* sTq = (int*)(sm + 22657);  // 64
    int* sTk = (int*)(sm + 22721);  // [2][64]

    int tid = threadIdx.x;
    int hofQ = 512 + head * 64, hofK = 768 + head * 64, hofV = 256 + head * 64;

    auto pfKV = [&](int kt, int buf) {
        int k0 = kt * 64;
        if (tid < 64) sTk[buf * 64 + tid] = ts[b * Nn + k0 + tid];
        float* dK = sKb + buf * 4608;
        float* dV = sVb + buf * 4352;
#pragma unroll
        for (int p = 0; p < 4; p++) {
            int l = tid + p * 256;
            int row = l >> 4, f4 = (l & 15) << 2;
            int c = row & 7;
            int prow = (row & ~7) | ((c & 1) ? 4 + (c >> 1) : (c >> 1));
            const float* src = &h[(size_t)(base + k0 + row) * 1024];
            cpa16(&dK[row * 72 + f4], src + hofK + f4);
            cpa16(&dV[prow * 68 + f4], src + hofV + f4);
        }
    };

    if (tid < 129) sW[tid] = ts_w[tid];
    if (tid < 64) sTq[tid] = ts[b * Nn + q0 + tid];
#pragma unroll
    for (int p = 0; p < 4; p++) {
        int l = tid + p * 256;
        int row = l >> 4, f4 = (l & 15) << 2;
        cpa16(&sQS[row * 72 + f4], &h[(size_t)(base + q0 + row) * 1024 + hofQ + f4]);
    }
    pfKV(kt0, 0);
    cpa_commit();

    int lane = tid & 31, wid = tid >> 5;
    int g = lane >> 2, t = lane & 3;
    int m0 = (wid >> 1) * 16, n0 = (wid & 1) * 32;
    int mgrp = wid >> 1;
    float o[4][4] = {};

    cpa_wait0();
    __syncthreads();

    // hoist Q fragments (h's q-section is alpha-permuted: pair (t,t+4) adjacent)
    float qf[8][4];
#pragma unroll
    for (int ks = 0; ks < 8; ks++) {
        float2 f0 = *reinterpret_cast<const float2*>(&sQS[(m0 + g) * 72 + ks * 8 + 2 * t]);
        float2 f1 = *reinterpret_cast<const float2*>(&sQS[(m0 + g + 8) * 72 + ks * 8 + 2 * t]);
        qf[ks][0] = f0.x; qf[ks][1] = f1.x; qf[ks][2] = f0.y; qf[ks][3] = f1.y;
    }
    __syncthreads();  // all Q frag reads done before sQS is reused as S

    for (int ii = 0; ii < nkt; ii++) {
        int kt = kt0 + ii;
        int buf = ii & 1;
        if (ii + 1 < nkt) { pfKV(kt + 1, buf ^ 1); cpa_commit(); }

        float* sK = sKb + buf * 4608;
        float* sV = sVb + buf * 4352;
        int* sTkb = sTk + buf * 64;
        int k0 = kt * 64;

        // ---- S = Q K^T ----
        float s4[4][4] = {};
#pragma unroll
        for (int ks = 0; ks < 8; ks++) {
#pragma unroll
            for (int j = 0; j < 4; j++) {
                float2 kb = *reinterpret_cast<const float2*>(
                    &sK[(n0 + 8 * j + g) * 72 + ks * 8 + 2 * t]);
                float bb[2] = {kb.x, kb.y};
                mma8(s4[j], qf[ks], bb);
            }
        }

        // ---- score: bias + silu + /N + causal; write S -> sQS ----
        int tq0 = sTq[m0 + g], tq1 = sTq[m0 + g + 8];
        int qg0 = q0 + m0 + g, qg1 = qg0 + 8;
#pragma unroll
        for (int j = 0; j < 4; j++) {
            int col = n0 + 8 * j + 2 * t;
            int tk0 = sTkb[col], tk1 = sTkb[col + 1];
            int kg0 = k0 + col, kg1 = kg0 + 1;
            float r[4];
            int tqs[4] = {tq0, tq0, tq1, tq1};
            int tks[4] = {tk0, tk1, tk0, tk1};
            int qgs[4] = {qg0, qg0, qg1, qg1};
            int kgs[4] = {kg0, kg1, kg0, kg1};
#pragma unroll
            for (int e = 0; e < 4; e++) {
                float ad = fabsf((float)(tqs[e] - tks[e]));
                int bk = (int)__logf(ad + 1.0f);
                bk = bk < 0 ? 0 : (bk > NBUCK ? NBUCK : bk);
                float z = s4[j][e] + sW[bk];
                z = __fdividef(z, 1.f + __expf(-z)) * INV_N;
                r[e] = (kgs[e] <= qgs[e]) ? z : 0.f;
            }
            *reinterpret_cast<float2*>(&sQS[(m0 + g) * 72 + col]) =
                make_float2(tf32r(r[0]), tf32r(r[1]));
            *reinterpret_cast<float2*>(&sQS[(m0 + g + 8) * 72 + col]) =
                make_float2(tf32r(r[2]), tf32r(r[3]));
        }
        // S rows are private to this m-group; sync only its 2 warps
        asm volatile("bar.sync %0, 64;" :: "r"(1 + mgrp));

        // ---- O += S V ---- (V rows permuted so (t,t+4) S-pairs are adjacent)
#pragma unroll
        for (int ks = 0; ks < 8; ks++) {
            float2 s0 = *reinterpret_cast<const float2*>(&sQS[(m0 + g) * 72 + ks * 8 + 2 * t]);
            float2 s1 = *reinterpret_cast<const float2*>(&sQS[(m0 + g + 8) * 72 + ks * 8 + 2 * t]);
            float a[4] = {s0.x, s1.x, s0.y, s1.y};
#pragma unroll
            for (int j = 0; j < 4; j++) {
                float bb[2];
                bb[0] = sV[(ks * 8 + t) * 68 + n0 + 8 * j + g];
                bb[1] = sV[(ks * 8 + t + 4) * 68 + n0 + 8 * j + g];
                mma8(o[j], a, bb);
            }
        }

        if (ii + 1 < nkt) { cpa_wait0(); __syncthreads(); }
    }

    // accumulate into g_attn
#pragma unroll
    for (int j = 0; j < 4; j++) {
        int col = head * 64 + n0 + 8 * j + 2 * t;
        float* p0 = &attn[(size_t)(base + q0 + m0 + g) * 256 + col];
        float* p1 = &attn[(size_t)(base + q0 + m0 + g + 8) * 256 + col];
        atomicAdd(p0, o[j][0]);
        atomicAdd(p0 + 1, o[j][1]);
        atomicAdd(p1, o[j][2]);
        atomicAdd(p1 + 1, o[j][3]);
    }
}

// ---------------------------------------------------------------------------
// o_in = tf32r(u * ln(attn)), warp-per-row
// ---------------------------------------------------------------------------
__global__ __launch_bounds__(256) void ln_u_kernel(const float* __restrict__ attn,
                                                   const float* __restrict__ h,
                                                   float* __restrict__ oin) {
    int row = blockIdx.x * 8 + (threadIdx.x >> 5);
    int lane = threadIdx.x & 31;
    const float* r = attn + (size_t)row * 256;
    float4 v[2];
    float s = 0.f, q = 0.f;
#pragma unroll
    for (int i = 0; i < 2; i++) {
        v[i] = *reinterpret_cast<const float4*>(&r[lane * 4 + i * 128]);
        s += v[i].x + v[i].y + v[i].z + v[i].w;
        q += v[i].x * v[i].x + v[i].y * v[i].y + v[i].z * v[i].z + v[i].w * v[i].w;
    }
#pragma unroll
    for (int o = 16; o > 0; o >>= 1) {
        s += __shfl_xor_sync(0xffffffffu, s, o);
        q += __shfl_xor_sync(0xffffffffu, q, o);
    }
    float m = s * (1.f / 256.f);
    float rstd = rsqrtf(q * (1.f / 256.f) - m * m + 1e-6f);
    float* ov = oin + (size_t)row * 256;
#pragma unroll
    for (int i = 0; i < 2; i++) {
        float4 u4 = *reinterpret_cast<const float4*>(
            &h[(size_t)row * 1024 + lane * 4 + i * 128]);
        float4 w;
        w.x = tf32r(u4.x * (v[i].x - m) * rstd);
        w.y = tf32r(u4.y * (v[i].y - m) * rstd);
        w.z = tf32r(u4.z * (v[i].z - m) * rstd);
        w.w = tf32r(u4.w * (v[i].w - m) * rstd);
        *reinterpret_cast<float4*>(&ov[lane * 4 + i * 128]) = w;
    }
}

// ---------------------------------------------------------------------------
// out = o_in @ o_w^T + o_b + x    tf32 MMA, 128x64 tile
// ---------------------------------------------------------------------------
__global__ __launch_bounds__(256) void gemm_out_kernel(const float* __restrict__ A,
                                                       const float* __restrict__ W,
                                                       const float* __restrict__ bias,
                                                       const float* __restrict__ x,
                                                       float* __restrict__ out) {
    __shared__ float sA[128][36];
    __shared__ float sB[32][65];
    int bm = blockIdx.y * 128, bn = blockIdx.x * 64;
    int tid = threadIdx.x, lane = tid & 31, wid = tid >> 5;
    int g = lane >> 2, t = lane & 3;
    int wm = (wid >> 1) * 32, wn = (wid & 1) * 32;
    float acc[2][4][4] = {};
    for (int k0 = 0; k0 < 256; k0 += 32) {
#pragma unroll
        for (int p = 0; p < 4; p++) {
            int idx = tid + p * 256;
            int row = idx >> 3, f4 = (idx & 7) << 2;
            float4 v = *reinterpret_cast<const float4*>(
                &A[(size_t)(bm + row) * 256 + k0 + f4]);
            *reinterpret_cast<float4*>(&sA[row][f4]) = v;
        }
#pragma unroll
        for (int p = 0; p < 2; p++) {
            int idx = tid + p * 256;
            int nr = idx >> 3, f4 = (idx & 7) << 2;
            float4 v = tf32r4(*reinterpret_cast<const float4*>(
                &W[(size_t)(bn + nr) * 256 + k0 + f4]));
            sB[f4 + 0][nr] = v.x; sB[f4 + 1][nr] = v.y;
            sB[f4 + 2][nr] = v.z; sB[f4 + 3][nr] = v.w;
        }
        __syncthreads();
#pragma unroll
        for (int kk = 0; kk < 32; kk += 8) {
            float a[2][4], bb[4][2];
#pragma unroll
            for (int i = 0; i < 2; i++) {
                int r = wm + 16 * i + g;
                a[i][0] = sA[r][kk + t];
                a[i][1] = sA[r + 8][kk + t];
                a[i][2] = sA[r][kk + t + 4];
                a[i][3] = sA[r + 8][kk + t + 4];
            }
#pragma unroll
            for (int j = 0; j < 4; j++) {
                bb[j][0] = sB[kk + t][wn + 8 * j + g];
                bb[j][1] = sB[kk + t + 4][wn + 8 * j + g];
            }
#pragma unroll
            for (int i = 0; i < 2; i++)
#pragma unroll
                for (int j = 0; j < 4; j++) mma8(acc[i][j], a[i], bb[j]);
        }
        __syncthreads();
    }
#pragma unroll
    for (int i = 0; i < 2; i++) {
        int r = bm + wm + 16 * i + g;
#pragma unroll
        for (int j = 0; j < 4; j++) {
            int c = bn + wn + 8 * j + 2 * t;
            float2 b2 = *reinterpret_cast<const float2*>(&bias[c]);
            float2 x0 = *reinterpret_cast<const float2*>(&x[(size_t)r * Dm + c]);
            float2 x1 = *reinterpret_cast<const float2*>(&x[(size_t)(r + 8) * Dm + c]);
            float* s = acc[i][j];
            *reinterpret_cast<float2*>(&out[(size_t)r * Dm + c]) =
                make_float2(s[0] + b2.x + x0.x, s[1] + b2.y + x0.y);
            *reinterpret_cast<float2*>(&out[(size_t)(r + 8) * Dm + c]) =
                make_float2(s[2] + b2.x + x1.x, s[3] + b2.y + x1.y);
        }
    }
}

// ---------------------------------------------------------------------------
extern "C" void kernel_launch(void* const* d_in, const int* in_sizes, int n_in,
                              void* d_out, int out_size) {
    const float* x    = (const float*)d_in[0];
    const float* uvqk = (const float*)d_in[1];
    const float* o_w  = (const float*)d_in[2];
    const float* o_b  = (const float*)d_in[3];
    const float* ts_w = (const float*)d_in[4];
    const int*   ts   = (const int*)d_in[5];
    float* out = (float*)d_out;

    float *xn, *uvqkr, *h, *attn, *oin;
    cudaGetSymbolAddress((void**)&xn,    g_xn);
    cudaGetSymbolAddress((void**)&uvqkr, g_uvqkr);
    cudaGetSymbolAddress((void**)&h,     g_h);
    cudaGetSymbolAddress((void**)&attn,  g_attn);
    cudaGetSymbolAddress((void**)&oin,   g_oin);

    cudaFuncSetAttribute(attn_kernel, cudaFuncAttributeMaxDynamicSharedMemorySize,
                         ATTN_SMEM);
    cudaFuncSetAttribute(gemm_silu_kernel, cudaFuncAttributeMaxDynamicSharedMemorySize,
                         G1_SMEM);

    cudaMemsetAsync(attn, 0, (size_t)T_ * 256 * sizeof(float));
    ln_x_kernel<<<800, 256>>>(x, xn);
    cvt_tf32_kernel<<<512, 256>>>((const float4*)uvqk, (float4*)uvqkr);
    gemm_silu_kernel<<<dim3(16, 50), 256, G1_SMEM>>>(xn, uvqkr, h);
    attn_kernel<<<dim3(216, 4), 256, ATTN_SMEM>>>(h, ts, ts_w, attn);
    ln_u_kernel<<<800, 256>>>(attn, h, oin);
    gemm_out_kernel<<<dim3(8, 50), 256>>>(oin, o_w, o_b, x, out);
}